// round 5
// baseline (speedup 1.0000x reference)
#include <cuda_runtime.h>
#include <cstdint>
#include <math.h>

#define NW 2048
#define TCC 12
#define TSS 4
#define HHd 128
#define Hd  256
#define Gd  512
#define WXD 768

typedef unsigned long long ull;

// ---------------- scratch (device globals; no allocation) ----------------
__device__ float g_X[TCC][NW][64];        // char/syl embeddings, t-major
__device__ float g_P[2][TCC][NW][Gd];     // input projections (gate-permuted layout)
__device__ float g_h2[2][2][NW][HHd];     // [buf][dir] double-buffered h
__device__ float g_c[2][NW][HHd];
__device__ float g_out[TCC][NW][Hd];      // bilstm outputs
__device__ float g_E[TCC][NW][Hd];        // attention energies (pre-tanh)
__device__ float g_score[TCC][NW];
__device__ float g_wordx[NW][WXD];        // [word_emb | char_ctx | syl_ctx]
__device__ float g_PW[2][NW][Gd];         // word LSTM input projections (natural layout)
__device__ float g_wout[NW][Hd];
__device__ float g_WhhP[2][Gd][HHd];      // gate-permuted Whh
__device__ float g_WihP[2][Gd][64];       // gate-permuted Wih
__device__ float g_bP[2][Gd];             // gate-permuted (bih+bhh)

// ---------------- fast math helpers ----------------
__device__ __forceinline__ float tanha(float x){
    float y; asm("tanh.approx.f32 %0, %1;" : "=f"(y) : "f"(x)); return y;
}
__device__ __forceinline__ float sigfast(float x){
    return fmaf(tanha(0.5f*x), 0.5f, 0.5f);
}
__device__ __forceinline__ ull ffma2(ull a, ull b, ull c){
    ull d;
    asm("fma.rn.f32x2 %0, %1, %2, %3;" : "=l"(d) : "l"(a), "l"(b), "l"(c));
    return d;
}
__device__ __forceinline__ ull pack2(float lo, float hi){
    ull d; asm("mov.b64 %0, {%1, %2};" : "=l"(d) : "f"(lo), "f"(hi)); return d;
}
__device__ __forceinline__ void unpack2(ull a, float& lo, float& hi){
    asm("mov.b64 {%0, %1}, %2;" : "=f"(lo), "=f"(hi) : "l"(a));
}
__device__ __forceinline__ float f2sum(ull a){
    float lo, hi; unpack2(a, lo, hi); return lo + hi;
}

// ---------------- gather kernels ----------------
__global__ void k_gatherX(const int* __restrict__ ids, const float* __restrict__ emb, int T){
    int idx = blockIdx.x*256 + threadIdx.x;
    int total = NW*T*64;
    if (idx >= total) return;
    int dcol = idx & 63;
    int r = idx >> 6;              // w*T + t
    int t = r % T, w = r / T;
    g_X[t][w][dcol] = emb[(size_t)ids[r]*64 + dcol];
}

__global__ void k_init(const int* __restrict__ feat, const float* __restrict__ embp){
    int idx = blockIdx.x*256 + threadIdx.x;   // 2*NW*HH = 524288
    int d = idx >> 18;
    int w = (idx >> 7) & (NW-1);
    int j = idx & 127;
    g_h2[0][d][w][j] = embp[(size_t)feat[w]*Hd + d*HHd + j];
    g_c[d][w][j] = 0.f;
}

__global__ void k_gatherW(const int* __restrict__ wid, const float* __restrict__ embw){
    int idx = blockIdx.x*256 + threadIdx.x;   // NW*256
    int w = idx >> 8, j = idx & 255;
    g_wordx[w][j] = embw[(size_t)wid[w]*256 + j];
}

// gate-interleave permutation: new row n = 4*j + g  <-  old row g*128 + j
__global__ void k_permW(const float* __restrict__ Wih, const float* __restrict__ Whh,
                        const float* __restrict__ bih, const float* __restrict__ bhh){
    int r = blockIdx.x*256 + threadIdx.x;   // 1024 rows
    if (r >= 1024) return;
    int d = r >> 9, n = r & 511;
    int g = n & 3, j = n >> 2;
    int oldr = g*128 + j;
    const float4* sh_ = (const float4*)(Whh + ((size_t)d*Gd + oldr)*HHd);
    float4* dh = (float4*)&g_WhhP[d][n][0];
    #pragma unroll
    for (int k=0;k<32;k++) dh[k] = sh_[k];
    const float4* si = (const float4*)(Wih + ((size_t)d*Gd + oldr)*64);
    float4* di = (float4*)&g_WihP[d][n][0];
    #pragma unroll
    for (int k=0;k<16;k++) di[k] = si[k];
    g_bP[d][n] = bih[d*Gd + oldr] + bhh[d*Gd + oldr];
}

// ---------------- big-tile GEMM: 128x128 block, 8x8 per thread, z-batched ----------------
// C = C0 + bias0 + bias1 + A @ B^T.  M%128==0, N%128==0, K%16==0.
__global__ __launch_bounds__(256) void k_gemm128(
    const float* __restrict__ A, const float* __restrict__ B,
    const float* __restrict__ bias0, const float* __restrict__ bias1,
    const float* __restrict__ C0, float* __restrict__ C,
    int M, int N, int K,
    long sB, long sBias, long sC0, long sC)
{
    __shared__ __align__(16) float As[2][16][136];
    __shared__ __align__(16) float Bs[2][16][136];
    long z = blockIdx.z;
    B += z*sB;
    if (bias0) bias0 += z*sBias;
    if (bias1) bias1 += z*sBias;
    if (C0) C0 += z*sC0;
    C += z*sC;
    int bn = blockIdx.x*128, bm = blockIdx.y*128;
    int tid = threadIdx.x;
    int tx = tid & 15, ty = tid >> 4;       // n-frag, m-frag
    int ar = tid >> 2, kc = (tid & 3) << 2; // loader: row 0..63, k 0..15 step 4

    const float* ApA = A + (size_t)(bm+ar)*K + kc;
    const float* ApB = A + (size_t)(bm+ar+64)*K + kc;
    const float* BpA = B + (size_t)(bn+ar)*K + kc;
    const float* BpB = B + (size_t)(bn+ar+64)*K + kc;

    {   // prime buffer 0
        float4 a0 = *(const float4*)ApA;
        float4 a1 = *(const float4*)ApB;
        float4 b0 = *(const float4*)BpA;
        float4 b1 = *(const float4*)BpB;
        #pragma unroll
        for (int j=0;j<4;j++){
            As[0][kc+j][ar]    = (&a0.x)[j];
            As[0][kc+j][ar+64] = (&a1.x)[j];
            Bs[0][kc+j][ar]    = (&b0.x)[j];
            Bs[0][kc+j][ar+64] = (&b1.x)[j];
        }
    }
    __syncthreads();

    ull acc[8][4] = {};
    int buf = 0;
    for (int k0 = 16; ; k0 += 16){
        bool more = (k0 < K);
        float4 na0, na1, nb0, nb1;
        if (more){
            na0 = *(const float4*)(ApA + k0);
            na1 = *(const float4*)(ApB + k0);
            nb0 = *(const float4*)(BpA + k0);
            nb1 = *(const float4*)(BpB + k0);
        }
        #pragma unroll
        for (int k=0;k<16;k++){
            float4 av0 = *(const float4*)&As[buf][k][ty<<3];
            float4 av1 = *(const float4*)&As[buf][k][(ty<<3)+4];
            ulonglong2 bv0 = *(const ulonglong2*)&Bs[buf][k][tx<<3];
            ulonglong2 bv1 = *(const ulonglong2*)&Bs[buf][k][(tx<<3)+4];
            ull bp4[4] = { bv0.x, bv0.y, bv1.x, bv1.y };
            float am[8] = { av0.x,av0.y,av0.z,av0.w, av1.x,av1.y,av1.z,av1.w };
            #pragma unroll
            for (int i=0;i<8;i++){
                ull ai = pack2(am[i], am[i]);
                #pragma unroll
                for (int j=0;j<4;j++)
                    acc[i][j] = ffma2(ai, bp4[j], acc[i][j]);
            }
        }
        if (!more) break;
        int nb = buf ^ 1;
        #pragma unroll
        for (int j=0;j<4;j++){
            As[nb][kc+j][ar]    = (&na0.x)[j];
            As[nb][kc+j][ar+64] = (&na1.x)[j];
            Bs[nb][kc+j][ar]    = (&nb0.x)[j];
            Bs[nb][kc+j][ar+64] = (&nb1.x)[j];
        }
        __syncthreads();
        buf = nb;
    }

    int n0 = bn + (tx<<3);
    float bb[8];
    #pragma unroll
    for (int j=0;j<8;j++) bb[j] = 0.f;
    if (bias0){
        #pragma unroll
        for (int j=0;j<8;j++) bb[j] = bias0[n0+j];
    }
    if (bias1){
        #pragma unroll
        for (int j=0;j<8;j++) bb[j] += bias1[n0+j];
    }
    #pragma unroll
    for (int i=0;i<8;i++){
        int m = bm + (ty<<3) + i;
        float c8[8];
        #pragma unroll
        for (int j=0;j<4;j++) unpack2(acc[i][j], c8[2*j], c8[2*j+1]);
        #pragma unroll
        for (int j=0;j<8;j++) c8[j] += bb[j];
        if (C0){
            float4 p0 = *(const float4*)&C0[(size_t)m*N + n0];
            float4 p1 = *(const float4*)&C0[(size_t)m*N + n0 + 4];
            c8[0]+=p0.x; c8[1]+=p0.y; c8[2]+=p0.z; c8[3]+=p0.w;
            c8[4]+=p1.x; c8[5]+=p1.y; c8[6]+=p1.z; c8[7]+=p1.w;
        }
        *(float4*)&C[(size_t)m*N + n0]     = make_float4(c8[0],c8[1],c8[2],c8[3]);
        *(float4*)&C[(size_t)m*N + n0 + 4] = make_float4(c8[4],c8[5],c8[6],c8[7]);
    }
}

// ---------------- fused recurrence GEMM + LSTM pointwise (gate-permuted, 64x64) ----------------
__global__ __launch_bounds__(256) void k_recfused(int s, int T){
    __shared__ __align__(16) float As[2][16][68];
    __shared__ __align__(16) float Bs[2][16][68];
    int d = blockIdx.z;
    int t = d ? (T-1-s) : s;
    int buf0 = s & 1;
    const float* A  = &g_h2[buf0][d][0][0];
    const float* B  = &g_WhhP[d][0][0];
    const float* C0 = &g_P[d][t][0][0];
    int bn = blockIdx.x*64, bm = blockIdx.y*64;
    int tid = threadIdx.x;
    int tx = tid & 15, ty = tid >> 4;
    int lr = tid >> 2, lc = (tid & 3) << 2;
    const float* Ap = A + (size_t)(bm+lr)*HHd + lc;
    const float* Bp = B + (size_t)(bn+lr)*HHd + lc;

    {
        float4 a = *(const float4*)Ap;
        float4 b = *(const float4*)Bp;
        As[0][lc+0][lr]=a.x; As[0][lc+1][lr]=a.y; As[0][lc+2][lr]=a.z; As[0][lc+3][lr]=a.w;
        Bs[0][lc+0][lr]=b.x; Bs[0][lc+1][lr]=b.y; Bs[0][lc+2][lr]=b.z; Bs[0][lc+3][lr]=b.w;
    }
    __syncthreads();

    ull acc[4][2] = {};
    int buf = 0;
    #pragma unroll
    for (int k0 = 16; ; k0 += 16){
        bool more = (k0 < HHd);
        float4 an, bn2;
        if (more){ an = *(const float4*)(Ap + k0); bn2 = *(const float4*)(Bp + k0); }
        #pragma unroll
        for (int k=0;k<16;k++){
            float4 av = *(const float4*)&As[buf][k][ty<<2];
            ulonglong2 bv = *(const ulonglong2*)&Bs[buf][k][tx<<2];
            ull a0 = pack2(av.x, av.x);
            ull a1 = pack2(av.y, av.y);
            ull a2 = pack2(av.z, av.z);
            ull a3 = pack2(av.w, av.w);
            acc[0][0]=ffma2(a0,bv.x,acc[0][0]); acc[0][1]=ffma2(a0,bv.y,acc[0][1]);
            acc[1][0]=ffma2(a1,bv.x,acc[1][0]); acc[1][1]=ffma2(a1,bv.y,acc[1][1]);
            acc[2][0]=ffma2(a2,bv.x,acc[2][0]); acc[2][1]=ffma2(a2,bv.y,acc[2][1]);
            acc[3][0]=ffma2(a3,bv.x,acc[3][0]); acc[3][1]=ffma2(a3,bv.y,acc[3][1]);
        }
        if (!more) break;
        int nb = buf ^ 1;
        As[nb][lc+0][lr]=an.x;  As[nb][lc+1][lr]=an.y;  As[nb][lc+2][lr]=an.z;  As[nb][lc+3][lr]=an.w;
        Bs[nb][lc+0][lr]=bn2.x; Bs[nb][lc+1][lr]=bn2.y; Bs[nb][lc+2][lr]=bn2.z; Bs[nb][lc+3][lr]=bn2.w;
        __syncthreads();
        buf = nb;
    }

    int n0 = bn + (tx<<2);
    int j = n0 >> 2;               // columns n0..n0+3 = gates i,f,g,o of hidden unit j
    #pragma unroll
    for (int i=0;i<4;i++){
        int m = bm + (ty<<2) + i;
        float4 p = *(const float4*)&C0[(size_t)m*Gd + n0];
        float gi,gf,gg,go;
        unpack2(acc[i][0], gi, gf);
        unpack2(acc[i][1], gg, go);
        gi += p.x; gf += p.y; gg += p.z; go += p.w;
        float c = sigfast(gf)*g_c[d][m][j] + sigfast(gi)*tanha(gg);
        float h = sigfast(go)*tanha(c);
        g_c[d][m][j] = c;
        g_h2[buf0^1][d][m][j] = h;
        g_out[t][m][d*HHd + j] = h;
    }
}

// ---------------- attention score ----------------
__global__ void k_score(int T, const float* __restrict__ wv){
    int gw = blockIdx.x*8 + (threadIdx.x >> 5);
    int lane = threadIdx.x & 31;
    if (gw >= T*NW) return;
    const float* e = &g_E[0][0][0] + (size_t)gw*Hd;
    float a = 0.f;
    #pragma unroll
    for (int i=0;i<8;i++){
        int g = lane + i*32;
        a += tanha(e[g]) * wv[g];
    }
    #pragma unroll
    for (int o=16;o;o>>=1) a += __shfl_xor_sync(0xffffffffu, a, o);
    if (lane == 0) (&g_score[0][0])[gw] = a;
}

// ---------------- softmax over t + weighted context ----------------
__global__ void k_softctx(int T, int off){
    int w = blockIdx.x, tid = threadIdx.x;    // 256 threads
    __shared__ float sc[TCC];
    if (tid < T) sc[tid] = g_score[tid][w];
    __syncthreads();
    float m = -1e30f;
    for (int t=0;t<T;t++) m = fmaxf(m, sc[t]);
    float den = 0.f, acc = 0.f;
    for (int t=0;t<T;t++){
        float e = expf(sc[t]-m);
        den += e;
        acc += e * g_out[t][w][tid];
    }
    g_wordx[w][off + tid] = acc/den;
}

// ---------------- word-level sequential BiLSTM ----------------
// 2 blocks (dir), 256 threads, 2 gate-rows/thread (r0=t, r1=t+256, natural layout).
// Per row: 88 weights in regs (44 ull), 40 weights in smem.
// smem weights interleaved per-thread: sW2[t][84]: [q*8+0..3]=row0 w[88+4q], [q*8+4..7]=row1 w[88+4q].
// stride 84 floats = 21 16B-chunks, gcd(21,32)=1 -> conflict-free LDS.128.
__global__ __launch_bounds__(256,1) void k_wordrec(
    const float* __restrict__ Whh, const float* __restrict__ PW, float* __restrict__ wout)
{
    extern __shared__ float smem[];
    float* sW2 = smem;                 // [256][84]
    float* sh  = smem + 256*84;        // h [128]
    float* scc = sh + 128;             // c [128]
    float* sg  = scc + 128;            // gates [512]
    int dir = blockIdx.x;
    int t0  = threadIdx.x;
    int r0 = t0, r1 = t0 + 256;
    const float* row0 = Whh + ((size_t)dir*Gd + r0)*HHd;
    const float* row1 = Whh + ((size_t)dir*Gd + r1)*HHd;

    ull wa[44], wb[44];
    {
        const ulonglong2* p0 = (const ulonglong2*)row0;
        const ulonglong2* p1 = (const ulonglong2*)row1;
        #pragma unroll
        for (int i=0;i<22;i++){
            ulonglong2 v0 = p0[i]; wa[2*i] = v0.x; wa[2*i+1] = v0.y;
            ulonglong2 v1 = p1[i]; wb[2*i] = v1.x; wb[2*i+1] = v1.y;
        }
    }
    #pragma unroll
    for (int q=0;q<10;q++){
        *(float4*)&sW2[t0*84 + q*8]     = *(const float4*)&row0[88 + q*4];
        *(float4*)&sW2[t0*84 + q*8 + 4] = *(const float4*)&row1[88 + q*4];
    }
    if (t0 < 128){ sh[t0] = 0.f; scc[t0] = 0.f; }
    const float* PWd = PW + (size_t)dir*NW*Gd;
    __syncthreads();

    for (int s=0;s<NW;s++){
        int t = dir ? (NW-1-s) : s;
        float pv0 = __ldg(&PWd[(size_t)t*Gd + r0]);
        float pv1 = __ldg(&PWd[(size_t)t*Gd + r1]);
        ull a0=0ull, a1=0ull, a2=0ull, a3=0ull;
        const ulonglong2* hp = (const ulonglong2*)sh;
        #pragma unroll
        for (int q=0;q<22;q++){
            ulonglong2 h2 = hp[q];            // h[4q..4q+3]
            a0 = ffma2(wa[2*q],   h2.x, a0);
            a1 = ffma2(wa[2*q+1], h2.y, a1);
            a2 = ffma2(wb[2*q],   h2.x, a2);
            a3 = ffma2(wb[2*q+1], h2.y, a3);
        }
        #pragma unroll
        for (int q=0;q<10;q++){
            ulonglong2 h2 = hp[22+q];         // h[88+4q..91+4q]
            ulonglong2 w0 = *(const ulonglong2*)&sW2[t0*84 + q*8];
            ulonglong2 w1 = *(const ulonglong2*)&sW2[t0*84 + q*8 + 4];
            a0 = ffma2(w0.x, h2.x, a0);
            a1 = ffma2(w0.y, h2.y, a1);
            a2 = ffma2(w1.x, h2.x, a2);
            a3 = ffma2(w1.y, h2.y, a3);
        }
        sg[r0] = pv0 + f2sum(a0) + f2sum(a1);
        sg[r1] = pv1 + f2sum(a2) + f2sum(a3);
        __syncthreads();
        if (t0 < 128){
            float i_ = sg[t0], f_ = sg[128+t0], g_ = sg[256+t0], o_ = sg[384+t0];
            float c = sigfast(f_)*scc[t0] + sigfast(i_)*tanha(g_);
            float h = sigfast(o_)*tanha(c);
            scc[t0] = c; sh[t0] = h;
            wout[(size_t)t*Hd + dir*HHd + t0] = h;
        }
        __syncthreads();
    }
}

// ---------------- final linear heads + log_softmax ----------------
__global__ void k_head(const float* __restrict__ wout,
                       const float* __restrict__ Wp, const float* __restrict__ bp,
                       const float* __restrict__ Wn, const float* __restrict__ bn_,
                       float* __restrict__ out)
{
    int w = blockIdx.x, tid = threadIdx.x;    // 64 threads
    __shared__ float h[Hd];
    __shared__ float lg[60];
    for (int i=tid;i<Hd;i+=64) h[i] = wout[w*Hd + i];
    __syncthreads();
    if (tid < 47){
        float a = bp[tid];
        const float* r = Wp + (size_t)tid*Hd;
        for (int k=0;k<Hd;k++) a += h[k]*r[k];
        lg[tid] = a;
    } else if (tid < 60){
        int n = tid-47;
        float a = bn_[n];
        const float* r = Wn + (size_t)n*Hd;
        for (int k=0;k<Hd;k++) a += h[k]*r[k];
        lg[tid] = a;
    }
    __syncthreads();
    if (tid < 47){
        float m = -1e30f;
        for (int i=0;i<47;i++) m = fmaxf(m, lg[i]);
        float s = 0.f;
        for (int i=0;i<47;i++) s += expf(lg[i]-m);
        out[(size_t)w*47 + tid] = lg[tid] - m - logf(s);
    } else if (tid < 60){
        float m = -1e30f;
        for (int i=47;i<60;i++) m = fmaxf(m, lg[i]);
        float s = 0.f;
        for (int i=47;i<60;i++) s += expf(lg[i]-m);
        out[(size_t)NW*47 + (size_t)w*13 + (tid-47)] = lg[tid] - m - logf(s);
    }
}

// ---------------- orchestration ----------------
extern "C" void kernel_launch(void* const* d_in, const int* in_sizes, int n_in,
                              void* d_out, int out_size)
{
    const int*   word_seq = (const int*)  d_in[0];
    const int*   syl_seq  = (const int*)  d_in[1];
    const int*   char_seq = (const int*)  d_in[2];
    const int*   feat_seq = (const int*)  d_in[3];
    const float* emb_char = (const float*)d_in[4];
    const float* emb_syl  = (const float*)d_in[5];
    const float* emb_word = (const float*)d_in[6];
    const float* emb_pref = (const float*)d_in[7];
    const float* aW_c = (const float*)d_in[8];
    const float* ab_c = (const float*)d_in[9];
    const float* aw_c = (const float*)d_in[10];
    const float* aW_s = (const float*)d_in[11];
    const float* ab_s = (const float*)d_in[12];
    const float* aw_s = (const float*)d_in[13];
    const float* cWih = (const float*)d_in[14];
    const float* cWhh = (const float*)d_in[15];
    const float* cbih = (const float*)d_in[16];
    const float* cbhh = (const float*)d_in[17];
    const float* sWih = (const float*)d_in[18];
    const float* sWhh = (const float*)d_in[19];
    const float* sbih = (const float*)d_in[20];
    const float* sbhh = (const float*)d_in[21];
    const float* wWih = (const float*)d_in[22];
    const float* wWhh = (const float*)d_in[23];
    const float* wbih = (const float*)d_in[24];
    const float* wbhh = (const float*)d_in[25];
    const float* Wp = (const float*)d_in[26];
    const float* bp = (const float*)d_in[27];
    const float* Wn = (const float*)d_in[28];
    const float* bn = (const float*)d_in[29];
    float* out = (float*)d_out;

    float *pX, *pP, *pE, *pWX, *pPW, *pWout, *pWihP, *pbP, *pOut;
    cudaGetSymbolAddress((void**)&pX,    g_X);
    cudaGetSymbolAddress((void**)&pP,    g_P);
    cudaGetSymbolAddress((void**)&pE,    g_E);
    cudaGetSymbolAddress((void**)&pWX,   g_wordx);
    cudaGetSymbolAddress((void**)&pPW,   g_PW);
    cudaGetSymbolAddress((void**)&pWout, g_wout);
    cudaGetSymbolAddress((void**)&pWihP, g_WihP);
    cudaGetSymbolAddress((void**)&pbP,   g_bP);
    cudaGetSymbolAddress((void**)&pOut,  g_out);

    const int wr_smem = (256*84 + 128 + 128 + 512) * 4;  // 89088 B
    cudaFuncSetAttribute(k_wordrec, cudaFuncAttributeMaxDynamicSharedMemorySize, wr_smem);

    // ===== char + syl composition phases =====
    for (int phase = 0; phase < 2; phase++){
        int T            = phase == 0 ? TCC      : TSS;
        const int*   ids = phase == 0 ? char_seq : syl_seq;
        const float* emb = phase == 0 ? emb_char : emb_syl;
        const float* Wih = phase == 0 ? cWih : sWih;
        const float* Whh = phase == 0 ? cWhh : sWhh;
        const float* bih = phase == 0 ? cbih : sbih;
        const float* bhh = phase == 0 ? cbhh : sbhh;
        const float* aW  = phase == 0 ? aW_c : aW_s;
        const float* ab  = phase == 0 ? ab_c : ab_s;
        const float* aw  = phase == 0 ? aw_c : aw_s;
        int off          = phase == 0 ? 256 : 512;
        int M            = T * NW;

        k_permW<<<4, 256>>>(Wih, Whh, bih, bhh);
        k_init<<<2048, 256>>>(feat_seq, emb_pref);
        k_gatherX<<<(NW*T*64 + 255)/256, 256>>>(ids, emb, T);

        // input projections, both directions in one launch (permuted layout)
        k_gemm128<<<dim3(Gd/128, M/128, 2), 256>>>(
            pX, pWihP, pbP, nullptr, nullptr, pP,
            M, Gd, 64,
            (long)Gd*64, (long)Gd, 0L, (long)TCC*NW*Gd);

        // recurrence: fused GEMM + LSTM update, both directions per launch
        for (int s = 0; s < T; s++)
            k_recfused<<<dim3(Gd/64, NW/64, 2), 256>>>(s, T);

        // attention
        k_gemm128<<<dim3(Hd/128, M/128, 1), 256>>>(pOut, aW, ab, nullptr, nullptr, pE,
                                                   M, Hd, Hd, 0L, 0L, 0L, 0L);
        k_score<<<(T*NW)/8, 256>>>(T, aw);
        k_softctx<<<NW, 256>>>(T, off);
    }

    // ===== word-level BiLSTM =====
    k_gatherW<<<NW, 256>>>(word_seq, emb_word);
    k_gemm128<<<dim3(Gd/128, NW/128, 2), 256>>>(
        pWX, wWih, wbih, wbhh, nullptr, pPW,
        NW, Gd, WXD,
        (long)Gd*WXD, (long)Gd, 0L, (long)NW*Gd);
    k_wordrec<<<2, 256, wr_smem>>>(wWhh, pPW, pWout);

    // ===== heads =====
    k_head<<<NW, 64>>>(pWout, Wp, bp, Wn, bn, out);
}

// round 6
// speedup vs baseline: 1.0820x; 1.0820x over previous
#include <cuda_runtime.h>
#include <cstdint>
#include <math.h>

#define NW 2048
#define TCC 12
#define TSS 4
#define HHd 128
#define Hd  256
#define Gd  512
#define WXD 768

typedef unsigned long long ull;

// ---------------- scratch (device globals; no allocation) ----------------
__device__ float g_X[TCC][NW][64];        // char/syl embeddings, t-major
__device__ float g_P[2][TCC][NW][Gd];     // input projections (gate-permuted layout)
__device__ float g_h2[2][2][NW][HHd];     // [buf][dir] double-buffered h
__device__ float g_c[2][NW][HHd];
__device__ float g_out[TCC][NW][Hd];      // bilstm outputs
__device__ float g_E[TCC][NW][Hd];        // attention energies (pre-tanh)
__device__ float g_score[TCC][NW];
__device__ float g_wordx[NW][WXD];        // [word_emb | char_ctx | syl_ctx]
__device__ float g_PW[2][NW][Gd];         // word LSTM input projections (natural layout)
__device__ float g_wout[NW][Hd];
__device__ float g_WhhP[2][Gd][HHd];      // gate-permuted Whh
__device__ float g_WihP[2][Gd][64];       // gate-permuted Wih
__device__ float g_bP[2][Gd];             // gate-permuted (bih+bhh)

// ---------------- fast math helpers ----------------
__device__ __forceinline__ float tanha(float x){
    float y; asm("tanh.approx.f32 %0, %1;" : "=f"(y) : "f"(x)); return y;
}
__device__ __forceinline__ float sigfast(float x){
    return fmaf(tanha(0.5f*x), 0.5f, 0.5f);
}
__device__ __forceinline__ ull ffma2(ull a, ull b, ull c){
    ull d;
    asm("fma.rn.f32x2 %0, %1, %2, %3;" : "=l"(d) : "l"(a), "l"(b), "l"(c));
    return d;
}
__device__ __forceinline__ ull pack2(float lo, float hi){
    ull d; asm("mov.b64 %0, {%1, %2};" : "=l"(d) : "f"(lo), "f"(hi)); return d;
}
__device__ __forceinline__ void unpack2(ull a, float& lo, float& hi){
    asm("mov.b64 {%0, %1}, %2;" : "=f"(lo), "=f"(hi) : "l"(a));
}
__device__ __forceinline__ float f2sum(ull a){
    float lo, hi; unpack2(a, lo, hi); return lo + hi;
}

// ---------------- gather kernels ----------------
__global__ void k_gatherX(const int* __restrict__ ids, const float* __restrict__ emb, int T){
    int idx = blockIdx.x*256 + threadIdx.x;
    int total = NW*T*64;
    if (idx >= total) return;
    int dcol = idx & 63;
    int r = idx >> 6;              // w*T + t
    int t = r % T, w = r / T;
    g_X[t][w][dcol] = emb[(size_t)ids[r]*64 + dcol];
}

__global__ void k_init(const int* __restrict__ feat, const float* __restrict__ embp){
    int idx = blockIdx.x*256 + threadIdx.x;   // 2*NW*HH = 524288
    int d = idx >> 18;
    int w = (idx >> 7) & (NW-1);
    int j = idx & 127;
    g_h2[0][d][w][j] = embp[(size_t)feat[w]*Hd + d*HHd + j];
    g_c[d][w][j] = 0.f;
}

__global__ void k_gatherW(const int* __restrict__ wid, const float* __restrict__ embw){
    int idx = blockIdx.x*256 + threadIdx.x;   // NW*256
    int w = idx >> 8, j = idx & 255;
    g_wordx[w][j] = embw[(size_t)wid[w]*256 + j];
}

// gate-interleave permutation: new row n = 4*j + g  <-  old row g*128 + j
__global__ void k_permW(const float* __restrict__ Wih, const float* __restrict__ Whh,
                        const float* __restrict__ bih, const float* __restrict__ bhh){
    int r = blockIdx.x*256 + threadIdx.x;   // 1024 rows
    if (r >= 1024) return;
    int d = r >> 9, n = r & 511;
    int g = n & 3, j = n >> 2;
    int oldr = g*128 + j;
    const float4* sh_ = (const float4*)(Whh + ((size_t)d*Gd + oldr)*HHd);
    float4* dh = (float4*)&g_WhhP[d][n][0];
    #pragma unroll
    for (int k=0;k<32;k++) dh[k] = sh_[k];
    const float4* si = (const float4*)(Wih + ((size_t)d*Gd + oldr)*64);
    float4* di = (float4*)&g_WihP[d][n][0];
    #pragma unroll
    for (int k=0;k<16;k++) di[k] = si[k];
    g_bP[d][n] = bih[d*Gd + oldr] + bhh[d*Gd + oldr];
}

// ---------------- GEMM: 128x64 block tile, 8x4 per-thread frag, z-batched ----------------
// C = C0 + bias0 + bias1 + A @ B^T.  M%128==0, N%64==0, K%16==0.
__global__ __launch_bounds__(256) void k_gemm(
    const float* __restrict__ A, const float* __restrict__ B,
    const float* __restrict__ bias0, const float* __restrict__ bias1,
    const float* __restrict__ C0, float* __restrict__ C,
    int M, int N, int K,
    long sB, long sBias, long sC0, long sC)
{
    __shared__ __align__(16) float As[2][16][136];
    __shared__ __align__(16) float Bs[2][16][72];
    long z = blockIdx.z;
    B += z*sB;
    if (bias0) bias0 += z*sBias;
    if (bias1) bias1 += z*sBias;
    if (C0) C0 += z*sC0;
    C += z*sC;
    int bn = blockIdx.x*64, bm = blockIdx.y*128;
    int tid = threadIdx.x;
    int tx = tid & 15, ty = tid >> 4;         // n-frag (4), m-frag (8)
    int ar = tid >> 1, ka = (tid & 1) << 3;   // A loader: row 0..127, k 0/8
    int br = tid >> 2, kb = (tid & 3) << 2;   // B loader: row 0..63,  k 0/4/8/12

    const float* Ap = A + (size_t)(bm+ar)*K + ka;
    const float* Bp = B + (size_t)(bn+br)*K + kb;

    {   // prime buffer 0
        float4 a0 = *(const float4*)Ap;
        float4 a1 = *(const float4*)(Ap+4);
        float4 b0 = *(const float4*)Bp;
        #pragma unroll
        for (int j=0;j<4;j++){
            As[0][ka+j][ar]   = (&a0.x)[j];
            As[0][ka+4+j][ar] = (&a1.x)[j];
            Bs[0][kb+j][br]   = (&b0.x)[j];
        }
    }
    __syncthreads();

    ull acc[8][2] = {};
    int buf = 0;
    for (int k0 = 16; ; k0 += 16){
        bool more = (k0 < K);
        float4 na0, na1, nb0;
        if (more){
            na0 = *(const float4*)(Ap + k0);
            na1 = *(const float4*)(Ap + k0 + 4);
            nb0 = *(const float4*)(Bp + k0);
        }
        #pragma unroll
        for (int k=0;k<16;k++){
            float4 av0 = *(const float4*)&As[buf][k][ty<<3];
            float4 av1 = *(const float4*)&As[buf][k][(ty<<3)+4];
            ulonglong2 bv = *(const ulonglong2*)&Bs[buf][k][tx<<2];
            float am[8] = { av0.x,av0.y,av0.z,av0.w, av1.x,av1.y,av1.z,av1.w };
            #pragma unroll
            for (int i=0;i<8;i++){
                ull ai = pack2(am[i], am[i]);
                acc[i][0] = ffma2(ai, bv.x, acc[i][0]);
                acc[i][1] = ffma2(ai, bv.y, acc[i][1]);
            }
        }
        if (!more) break;
        int nb = buf ^ 1;
        #pragma unroll
        for (int j=0;j<4;j++){
            As[nb][ka+j][ar]   = (&na0.x)[j];
            As[nb][ka+4+j][ar] = (&na1.x)[j];
            Bs[nb][kb+j][br]   = (&nb0.x)[j];
        }
        __syncthreads();
        buf = nb;
    }

    int n0 = bn + (tx<<2);
    float bb[4] = {0.f,0.f,0.f,0.f};
    if (bias0){ bb[0]=bias0[n0]; bb[1]=bias0[n0+1]; bb[2]=bias0[n0+2]; bb[3]=bias0[n0+3]; }
    if (bias1){ bb[0]+=bias1[n0]; bb[1]+=bias1[n0+1]; bb[2]+=bias1[n0+2]; bb[3]+=bias1[n0+3]; }
    #pragma unroll
    for (int i=0;i<8;i++){
        int m = bm + (ty<<3) + i;
        float4 v;
        unpack2(acc[i][0], v.x, v.y);
        unpack2(acc[i][1], v.z, v.w);
        v.x += bb[0]; v.y += bb[1]; v.z += bb[2]; v.w += bb[3];
        if (C0){
            float4 c0 = *(const float4*)&C0[(size_t)m*N + n0];
            v.x += c0.x; v.y += c0.y; v.z += c0.z; v.w += c0.w;
        }
        *(float4*)&C[(size_t)m*N + n0] = v;
    }
}

// ---------------- fused recurrence GEMM + LSTM pointwise (gate-permuted, 128x64) ----------------
__global__ __launch_bounds__(256) void k_recfused(int s, int T){
    __shared__ __align__(16) float As[2][16][136];
    __shared__ __align__(16) float Bs[2][16][72];
    int d = blockIdx.z;
    int t = d ? (T-1-s) : s;
    int buf0 = s & 1;
    const float* A  = &g_h2[buf0][d][0][0];   // [NW][128]
    const float* B  = &g_WhhP[d][0][0];       // [512][128]
    const float* C0 = &g_P[d][t][0][0];       // [NW][512]
    int bn = blockIdx.x*64, bm = blockIdx.y*128;
    int tid = threadIdx.x;
    int tx = tid & 15, ty = tid >> 4;
    int ar = tid >> 1, ka = (tid & 1) << 3;
    int br = tid >> 2, kb = (tid & 3) << 2;

    const float* Ap = A + (size_t)(bm+ar)*HHd + ka;
    const float* Bp = B + (size_t)(bn+br)*HHd + kb;

    {
        float4 a0 = *(const float4*)Ap;
        float4 a1 = *(const float4*)(Ap+4);
        float4 b0 = *(const float4*)Bp;
        #pragma unroll
        for (int j=0;j<4;j++){
            As[0][ka+j][ar]   = (&a0.x)[j];
            As[0][ka+4+j][ar] = (&a1.x)[j];
            Bs[0][kb+j][br]   = (&b0.x)[j];
        }
    }
    __syncthreads();

    ull acc[8][2] = {};
    int buf = 0;
    #pragma unroll 2
    for (int k0 = 16; ; k0 += 16){
        bool more = (k0 < HHd);
        float4 na0, na1, nb0;
        if (more){
            na0 = *(const float4*)(Ap + k0);
            na1 = *(const float4*)(Ap + k0 + 4);
            nb0 = *(const float4*)(Bp + k0);
        }
        #pragma unroll
        for (int k=0;k<16;k++){
            float4 av0 = *(const float4*)&As[buf][k][ty<<3];
            float4 av1 = *(const float4*)&As[buf][k][(ty<<3)+4];
            ulonglong2 bv = *(const ulonglong2*)&Bs[buf][k][tx<<2];
            float am[8] = { av0.x,av0.y,av0.z,av0.w, av1.x,av1.y,av1.z,av1.w };
            #pragma unroll
            for (int i=0;i<8;i++){
                ull ai = pack2(am[i], am[i]);
                acc[i][0] = ffma2(ai, bv.x, acc[i][0]);
                acc[i][1] = ffma2(ai, bv.y, acc[i][1]);
            }
        }
        if (!more) break;
        int nb = buf ^ 1;
        #pragma unroll
        for (int j=0;j<4;j++){
            As[nb][ka+j][ar]   = (&na0.x)[j];
            As[nb][ka+4+j][ar] = (&na1.x)[j];
            Bs[nb][kb+j][br]   = (&nb0.x)[j];
        }
        __syncthreads();
        buf = nb;
    }

    int n0 = bn + (tx<<2);
    int j = n0 >> 2;               // columns n0..n0+3 = gates i,f,g,o of hidden unit j
    #pragma unroll
    for (int i=0;i<8;i++){
        int m = bm + (ty<<3) + i;
        float4 p = *(const float4*)&C0[(size_t)m*Gd + n0];
        float gi,gf,gg,go;
        unpack2(acc[i][0], gi, gf);
        unpack2(acc[i][1], gg, go);
        gi += p.x; gf += p.y; gg += p.z; go += p.w;
        float c = sigfast(gf)*g_c[d][m][j] + sigfast(gi)*tanha(gg);
        float h = sigfast(go)*tanha(c);
        g_c[d][m][j] = c;
        g_h2[buf0^1][d][m][j] = h;
        g_out[t][m][d*HHd + j] = h;
    }
}

// ---------------- attention score ----------------
__global__ void k_score(int T, const float* __restrict__ wv){
    int gw = blockIdx.x*8 + (threadIdx.x >> 5);
    int lane = threadIdx.x & 31;
    if (gw >= T*NW) return;
    const float* e = &g_E[0][0][0] + (size_t)gw*Hd;
    float a = 0.f;
    #pragma unroll
    for (int i=0;i<8;i++){
        int g = lane + i*32;
        a += tanha(e[g]) * wv[g];
    }
    #pragma unroll
    for (int o=16;o;o>>=1) a += __shfl_xor_sync(0xffffffffu, a, o);
    if (lane == 0) (&g_score[0][0])[gw] = a;
}

// ---------------- softmax over t + weighted context ----------------
__global__ void k_softctx(int T, int off){
    int w = blockIdx.x, tid = threadIdx.x;    // 256 threads
    __shared__ float sc[TCC];
    if (tid < T) sc[tid] = g_score[tid][w];
    __syncthreads();
    float m = -1e30f;
    for (int t=0;t<T;t++) m = fmaxf(m, sc[t]);
    float den = 0.f, acc = 0.f;
    for (int t=0;t<T;t++){
        float e = expf(sc[t]-m);
        den += e;
        acc += e * g_out[t][w][tid];
    }
    g_wordx[w][off + tid] = acc/den;
}

// ---------------- word-level sequential BiLSTM ----------------
// 2 blocks (dir), 256 threads, 2 gate-rows/thread (r0=t, r1=t+256, natural layout).
// Per row: 100 weights in regs (50 ull), 28 weights in smem.
// sW2[t][60]: [0..27]=row0 w[100..127], [28..55]=row1 w[100..127]; stride 60 floats
// = 15 16B-chunks, gcd(15,32)=1 -> conflict-free LDS.128 across lanes.
__global__ __launch_bounds__(256,1) void k_wordrec(
    const float* __restrict__ Whh, const float* __restrict__ PW, float* __restrict__ wout)
{
    extern __shared__ float smem[];
    float* sW2 = smem;                 // [256][60]
    float* sh  = smem + 256*60;        // h [128]
    float* scc = sh + 128;             // c [128]
    float* sg  = scc + 128;            // gates [512]
    int dir = blockIdx.x;
    int t0  = threadIdx.x;
    int r0 = t0, r1 = t0 + 256;
    const float* row0 = Whh + ((size_t)dir*Gd + r0)*HHd;
    const float* row1 = Whh + ((size_t)dir*Gd + r1)*HHd;

    ull wa[50], wb[50];
    {
        const ulonglong2* p0 = (const ulonglong2*)row0;
        const ulonglong2* p1 = (const ulonglong2*)row1;
        #pragma unroll
        for (int i=0;i<25;i++){
            ulonglong2 v0 = p0[i]; wa[2*i] = v0.x; wa[2*i+1] = v0.y;
            ulonglong2 v1 = p1[i]; wb[2*i] = v1.x; wb[2*i+1] = v1.y;
        }
    }
    #pragma unroll
    for (int q=0;q<7;q++){
        *(float4*)&sW2[t0*60 + q*4]      = *(const float4*)&row0[100 + q*4];
        *(float4*)&sW2[t0*60 + 28 + q*4] = *(const float4*)&row1[100 + q*4];
    }
    if (t0 < 128){ sh[t0] = 0.f; scc[t0] = 0.f; }
    const float* PWd = PW + (size_t)dir*NW*Gd;
    __syncthreads();

    for (int s=0;s<NW;s++){
        int t = dir ? (NW-1-s) : s;
        float pv0 = __ldg(&PWd[(size_t)t*Gd + r0]);
        float pv1 = __ldg(&PWd[(size_t)t*Gd + r1]);
        ull a0=0ull, a1=0ull, a2=0ull, a3=0ull;
        const ulonglong2* hp = (const ulonglong2*)sh;
        #pragma unroll
        for (int q=0;q<25;q++){
            ulonglong2 h2 = hp[q];            // h[4q..4q+3]
            a0 = ffma2(wa[2*q],   h2.x, a0);
            a1 = ffma2(wa[2*q+1], h2.y, a1);
            a2 = ffma2(wb[2*q],   h2.x, a2);
            a3 = ffma2(wb[2*q+1], h2.y, a3);
        }
        #pragma unroll
        for (int q=0;q<7;q++){
            ulonglong2 h2 = hp[25+q];         // h[100+4q..103+4q]
            ulonglong2 w0 = *(const ulonglong2*)&sW2[t0*60 + q*4];
            ulonglong2 w1 = *(const ulonglong2*)&sW2[t0*60 + 28 + q*4];
            a0 = ffma2(w0.x, h2.x, a0);
            a1 = ffma2(w0.y, h2.y, a1);
            a2 = ffma2(w1.x, h2.x, a2);
            a3 = ffma2(w1.y, h2.y, a3);
        }
        sg[r0] = pv0 + f2sum(a0) + f2sum(a1);
        sg[r1] = pv1 + f2sum(a2) + f2sum(a3);
        __syncthreads();
        if (t0 < 128){
            float i_ = sg[t0], f_ = sg[128+t0], g_ = sg[256+t0], o_ = sg[384+t0];
            float c = sigfast(f_)*scc[t0] + sigfast(i_)*tanha(g_);
            float h = sigfast(o_)*tanha(c);
            scc[t0] = c; sh[t0] = h;
            wout[(size_t)t*Hd + dir*HHd + t0] = h;
        }
        __syncthreads();
    }
}

// ---------------- final linear heads + log_softmax ----------------
__global__ void k_head(const float* __restrict__ wout,
                       const float* __restrict__ Wp, const float* __restrict__ bp,
                       const float* __restrict__ Wn, const float* __restrict__ bn_,
                       float* __restrict__ out)
{
    int w = blockIdx.x, tid = threadIdx.x;    // 64 threads
    __shared__ float h[Hd];
    __shared__ float lg[60];
    for (int i=tid;i<Hd;i+=64) h[i] = wout[w*Hd + i];
    __syncthreads();
    if (tid < 47){
        float a = bp[tid];
        const float* r = Wp + (size_t)tid*Hd;
        for (int k=0;k<Hd;k++) a += h[k]*r[k];
        lg[tid] = a;
    } else if (tid < 60){
        int n = tid-47;
        float a = bn_[n];
        const float* r = Wn + (size_t)n*Hd;
        for (int k=0;k<Hd;k++) a += h[k]*r[k];
        lg[tid] = a;
    }
    __syncthreads();
    if (tid < 47){
        float m = -1e30f;
        for (int i=0;i<47;i++) m = fmaxf(m, lg[i]);
        float s = 0.f;
        for (int i=0;i<47;i++) s += expf(lg[i]-m);
        out[(size_t)w*47 + tid] = lg[tid] - m - logf(s);
    } else if (tid < 60){
        float m = -1e30f;
        for (int i=47;i<60;i++) m = fmaxf(m, lg[i]);
        float s = 0.f;
        for (int i=47;i<60;i++) s += expf(lg[i]-m);
        out[(size_t)NW*47 + (size_t)w*13 + (tid-47)] = lg[tid] - m - logf(s);
    }
}

// ---------------- orchestration ----------------
extern "C" void kernel_launch(void* const* d_in, const int* in_sizes, int n_in,
                              void* d_out, int out_size)
{
    const int*   word_seq = (const int*)  d_in[0];
    const int*   syl_seq  = (const int*)  d_in[1];
    const int*   char_seq = (const int*)  d_in[2];
    const int*   feat_seq = (const int*)  d_in[3];
    const float* emb_char = (const float*)d_in[4];
    const float* emb_syl  = (const float*)d_in[5];
    const float* emb_word = (const float*)d_in[6];
    const float* emb_pref = (const float*)d_in[7];
    const float* aW_c = (const float*)d_in[8];
    const float* ab_c = (const float*)d_in[9];
    const float* aw_c = (const float*)d_in[10];
    const float* aW_s = (const float*)d_in[11];
    const float* ab_s = (const float*)d_in[12];
    const float* aw_s = (const float*)d_in[13];
    const float* cWih = (const float*)d_in[14];
    const float* cWhh = (const float*)d_in[15];
    const float* cbih = (const float*)d_in[16];
    const float* cbhh = (const float*)d_in[17];
    const float* sWih = (const float*)d_in[18];
    const float* sWhh = (const float*)d_in[19];
    const float* sbih = (const float*)d_in[20];
    const float* sbhh = (const float*)d_in[21];
    const float* wWih = (const float*)d_in[22];
    const float* wWhh = (const float*)d_in[23];
    const float* wbih = (const float*)d_in[24];
    const float* wbhh = (const float*)d_in[25];
    const float* Wp = (const float*)d_in[26];
    const float* bp = (const float*)d_in[27];
    const float* Wn = (const float*)d_in[28];
    const float* bn = (const float*)d_in[29];
    float* out = (float*)d_out;

    float *pX, *pP, *pE, *pWX, *pPW, *pWout, *pWihP, *pbP, *pOut;
    cudaGetSymbolAddress((void**)&pX,    g_X);
    cudaGetSymbolAddress((void**)&pP,    g_P);
    cudaGetSymbolAddress((void**)&pE,    g_E);
    cudaGetSymbolAddress((void**)&pWX,   g_wordx);
    cudaGetSymbolAddress((void**)&pPW,   g_PW);
    cudaGetSymbolAddress((void**)&pWout, g_wout);
    cudaGetSymbolAddress((void**)&pWihP, g_WihP);
    cudaGetSymbolAddress((void**)&pbP,   g_bP);
    cudaGetSymbolAddress((void**)&pOut,  g_out);

    const int wr_smem = (256*60 + 128 + 128 + 512) * 4;  // 64512 B
    cudaFuncSetAttribute(k_wordrec, cudaFuncAttributeMaxDynamicSharedMemorySize, wr_smem);

    // ===== char + syl composition phases =====
    for (int phase = 0; phase < 2; phase++){
        int T            = phase == 0 ? TCC      : TSS;
        const int*   ids = phase == 0 ? char_seq : syl_seq;
        const float* emb = phase == 0 ? emb_char : emb_syl;
        const float* Wih = phase == 0 ? cWih : sWih;
        const float* Whh = phase == 0 ? cWhh : sWhh;
        const float* bih = phase == 0 ? cbih : sbih;
        const float* bhh = phase == 0 ? cbhh : sbhh;
        const float* aW  = phase == 0 ? aW_c : aW_s;
        const float* ab  = phase == 0 ? ab_c : ab_s;
        const float* aw  = phase == 0 ? aw_c : aw_s;
        int off          = phase == 0 ? 256 : 512;
        int M            = T * NW;

        k_permW<<<4, 256>>>(Wih, Whh, bih, bhh);
        k_init<<<2048, 256>>>(feat_seq, emb_pref);
        k_gatherX<<<(NW*T*64 + 255)/256, 256>>>(ids, emb, T);

        // input projections, both directions in one launch (permuted layout)
        k_gemm<<<dim3(Gd/64, M/128, 2), 256>>>(
            pX, pWihP, pbP, nullptr, nullptr, pP,
            M, Gd, 64,
            (long)Gd*64, (long)Gd, 0L, (long)TCC*NW*Gd);

        // recurrence: fused GEMM + LSTM update, both directions per launch
        for (int s = 0; s < T; s++)
            k_recfused<<<dim3(Gd/64, NW/128, 2), 256>>>(s, T);

        // attention
        k_gemm<<<dim3(Hd/64, M/128, 1), 256>>>(pOut, aW, ab, nullptr, nullptr, pE,
                                               M, Hd, Hd, 0L, 0L, 0L, 0L);
        k_score<<<(T*NW)/8, 256>>>(T, aw);
        k_softctx<<<NW, 256>>>(T, off);
    }

    // ===== word-level BiLSTM =====
    k_gatherW<<<NW, 256>>>(word_seq, emb_word);
    k_gemm<<<dim3(Gd/64, NW/128, 2), 256>>>(
        pWX, wWih, wbih, wbhh, nullptr, pPW,
        NW, Gd, WXD,
        (long)Gd*WXD, (long)Gd, 0L, (long)NW*Gd);
    k_wordrec<<<2, 256, wr_smem>>>(wWhh, pPW, pWout);

    // ===== heads =====
    k_head<<<NW, 64>>>(pWout, Wp, bp, Wn, bn, out);
}